// round 15
// baseline (speedup 1.0000x reference)
#include <cuda_runtime.h>
#include <cuda_bf16.h>
#include <cstdint>

// Problem constants
#define NB   32
#define CIN  256
#define COUT 256
#define H    56
#define W    56
#define HW   3136
#define HB   58   // padded rows (0..57)
#define WB   66   // padded cols (0..65)

// bf16 encodings of sign values
#define BF_P1 0x3F80u
#define BF_M1 0xBF80u

// conv staging: stage covers 64 ci: A = 128px x 128B, B = 256co x 128B
#define STG_A   16384
#define STG_SZ  49152
#define NSTAGE  3
#define SMEM_BUF_OFF 1024
#define SMEM_TOTAL   (1024 + NSTAGE * STG_SZ)   // 148480

// Scratch (bf16 sign values)
__device__ __align__(1024) uint16_t g_act[(size_t)NB * HB * WB * CIN];
__device__ __align__(1024) uint16_t g_wb[9 * COUT * CIN];

__device__ __forceinline__ uint16_t bsign(float v) {
    return (v > 0.f) ? (uint16_t)BF_P1 : ((v < 0.f) ? (uint16_t)BF_M1 : (uint16_t)0);
}

__device__ __forceinline__ uint32_t su32(const void* p) {
    return (uint32_t)__cvta_generic_to_shared(p);
}

#define CP16(dst, src) \
    asm volatile("cp.async.cg.shared.global [%0], [%1], 16;\n" :: "r"(dst), "l"(src))
#define CP_COMMIT() asm volatile("cp.async.commit_group;\n" ::: "memory")
#define CP_WAIT1()  asm volatile("cp.async.wait_group 1;\n" ::: "memory")

__device__ __forceinline__ void ldsm_x4(uint32_t* r, uint32_t addr) {
    asm volatile("ldmatrix.sync.aligned.m8n8.x4.shared.b16 {%0,%1,%2,%3}, [%4];"
                 : "=r"(r[0]), "=r"(r[1]), "=r"(r[2]), "=r"(r[3]) : "r"(addr));
}
__device__ __forceinline__ void mma_bf16(float* d, const uint32_t* a, const uint32_t* b) {
    asm volatile(
        "mma.sync.aligned.m16n8k16.row.col.f32.bf16.bf16.f32 "
        "{%0,%1,%2,%3}, {%4,%5,%6,%7}, {%8,%9}, {%0,%1,%2,%3};\n"
        : "+f"(d[0]), "+f"(d[1]), "+f"(d[2]), "+f"(d[3])
        : "r"(a[0]), "r"(a[1]), "r"(a[2]), "r"(a[3]), "r"(b[0]), "r"(b[1]));
}

// ---------------------------------------------------------------------------
// Zero padded borders of g_act (R7-proven).
// ---------------------------------------------------------------------------
__global__ void zero_border_kernel() {
    int idx = blockIdx.x * 256 + threadIdx.x;
    const int total = NB * 692 * 32;
    if (idx >= total) return;
    int word = idx & 31;
    int bp   = (idx >> 5) % 692;
    int n    = idx / (692 * 32);
    int yy, xx;
    if (bp < 66)       { yy = 0;  xx = bp; }
    else if (bp < 132) { yy = 57; xx = bp - 66; }
    else {
        int r = bp - 132;
        yy = 1 + r / 10;
        int c = r % 10;
        xx = (c == 0) ? 0 : (56 + c);
    }
    float4* p = reinterpret_cast<float4*>(g_act);
    p[((size_t)(n * HB + yy) * WB + xx) * 32 + word] = make_float4(0.f, 0.f, 0.f, 0.f);
}

// ---------------------------------------------------------------------------
// Binarize + transpose x (R7-proven).
// ---------------------------------------------------------------------------
__global__ void bin_act_kernel(const float* __restrict__ x) {
    __shared__ uint16_t t[32][33];
    int nz = blockIdx.z;
    int n = nz / H, y = nz % H;
    int x0 = blockIdx.x * 32;
    int c0 = blockIdx.y * 32;
    int tid = threadIdx.x;
    int tx = tid & 31, ty = tid >> 5;

    #pragma unroll
    for (int i = 0; i < 4; i++) {
        int ci = c0 + ty + i * 8;
        int xx = x0 + tx;
        float v = 0.f;
        if (xx < W)
            v = x[(((size_t)n * CIN + ci) * H + y) * W + xx];
        t[ty + i * 8][tx] = bsign(v);
    }
    __syncthreads();
    int pxi = tid >> 4;
    int cp  = tid & 15;
    #pragma unroll
    for (int j = 0; j < 2; j++) {
        int xl = pxi + j * 16;
        int xx = x0 + xl;
        if (xx < W) {
            uint32_t v = (uint32_t)t[cp * 2][xl] | ((uint32_t)t[cp * 2 + 1][xl] << 16);
            uint32_t* dst = reinterpret_cast<uint32_t*>(
                g_act + (((size_t)n * HB + (y + 1)) * WB + (xx + 1)) * CIN + c0);
            dst[cp] = v;
        }
    }
}

// ---------------------------------------------------------------------------
// Binarize weights: OIHW fp32 -> [tap][co][ci] bf16.
// ---------------------------------------------------------------------------
__global__ void bin_w_kernel(const float* __restrict__ M) {
    int o = blockIdx.x * 256 + threadIdx.x;
    int tap = o >> 16;
    int co  = (o >> 8) & 255;
    int ci  = o & 255;
    g_wb[o] = bsign(M[(size_t)(co * CIN + ci) * 9 + tap]);
}

// ---------------------------------------------------------------------------
// bf16 implicit-GEMM conv, fat warp tiles: CTA 128px x 256co, 8 warps in
// 2(M) x 4(N), warp tile 64x64 -> 0.125 ldsm-x4 per MMA (was 0.1875).
// K = 9*256 in 36 stages of 64 ci; 3-buffer cp.async pipeline.
// Epilogue: two 128-co smem-transpose passes (aliasing stage buffers).
// ---------------------------------------------------------------------------
__global__ void __launch_bounds__(256, 1)
conv_mma_kernel(const float* __restrict__ alpha, float* __restrict__ out) {
    extern __shared__ char smem[];
    uint32_t sb = su32(smem);
    float* alphaS = (float*)smem;                 // 1KB: all 256 alphas
    float* epi    = (float*)(smem + SMEM_BUF_OFF); // aliases buffers post-loop

    int tid  = threadIdx.x;
    int wid  = tid >> 5, lane = tid & 31;
    int p0   = blockIdx.x * 128;
    int n    = blockIdx.y;

    alphaS[tid] = alpha[tid];

    // ---- producer constants ----
    int pc = tid & 7;            // 16B chunk within 128B row (8 ci each)
    int pr = tid >> 3;           // base row 0..31
    uint32_t pdst = (uint32_t)(pr * 128) + (uint32_t)(((pc ^ (pr & 7)) << 4));
    size_t aoff[4];
    #pragma unroll
    for (int i = 0; i < 4; i++) {
        int p = p0 + pr + 32 * i;
        if (p > HW - 1) p = HW - 1;   // clamp tail tile
        int yy = p / W, xx = p - yy * W;
        aoff[i] = ((size_t)(n * HB + yy) * WB + xx) * CIN + pc * 8;
    }
    const uint16_t* gbBase = g_wb + (size_t)pr * CIN + pc * 8;

    auto produce = [&](int s) {
        if (s < 36) {
            int tap = s >> 2, q = s & 3;        // 64-ci quarter
            int kh = tap / 3, kw = tap - kh * 3;
            int tapoff = (kh * WB + kw) * CIN + q * 64;
            const uint16_t* gb = gbBase + ((size_t)tap * (COUT * CIN) + q * 64);
            uint32_t base = sb + SMEM_BUF_OFF + (uint32_t)((s % 3) * STG_SZ);
            uint32_t ad = base + pdst;
            uint32_t bd = base + STG_A + pdst;
            #pragma unroll
            for (int i = 0; i < 4; i++)      // A: 128 px rows
                CP16(ad + i * 4096, g_act + aoff[i] + tapoff);
            #pragma unroll
            for (int i = 0; i < 8; i++)      // B: 256 co rows
                CP16(bd + i * 4096, gb + (size_t)i * (32 * CIN));
        }
        CP_COMMIT();
    };

    produce(0);
    produce(1);

    // ---- consumer constants ----
    int mw = wid & 1;            // px half (64 px)
    int nw = wid >> 1;           // co quarter (64 co each)
    int rlA = (lane & 7) + ((lane >> 3) & 1) * 8;
    int hiA = lane >> 4;
    int swA = rlA & 7;
    int rlB = (lane & 7) + ((lane >> 4) & 1) * 8;
    int hiB = (lane >> 3) & 1;
    int swB = rlB & 7;

    float acc[4][8][4];
    #pragma unroll
    for (int mt = 0; mt < 4; mt++)
        #pragma unroll
        for (int nt = 0; nt < 8; nt++)
            #pragma unroll
            for (int c = 0; c < 4; c++) acc[mt][nt][c] = 0.f;

    for (int s = 0; s < 36; s++) {
        CP_WAIT1();
        __syncthreads();           // stage s resident; all warps done with s-1
        produce(s + 2);            // refill buf (s+2)%3 == (s-1)%3

        uint32_t aB = sb + SMEM_BUF_OFF + (uint32_t)((s % 3) * STG_SZ);
        uint32_t bB = aB + STG_A;
        #pragma unroll
        for (int kc = 0; kc < 4; kc++) {
            uint32_t a[4][4], b2[4][4];
            #pragma unroll
            for (int mt = 0; mt < 4; mt++) {
                uint32_t addr = aB + (uint32_t)((mw * 64 + mt * 16 + rlA) * 128)
                              + (uint32_t)((((kc * 2 + hiA) ^ swA) << 4));
                ldsm_x4(a[mt], addr);
            }
            #pragma unroll
            for (int np = 0; np < 4; np++) {   // 16 co each -> 64 co
                int row = nw * 64 + np * 16 + rlB;
                uint32_t addr = bB + (uint32_t)(row * 128)
                              + (uint32_t)((((kc * 2 + hiB) ^ swB) << 4));
                ldsm_x4(b2[np], addr);
            }
            #pragma unroll
            for (int mt = 0; mt < 4; mt++)
                #pragma unroll
                for (int nt = 0; nt < 8; nt++)
                    mma_bf16(acc[mt][nt], a[mt], &b2[nt >> 1][(nt & 1) * 2]);
        }
    }

    // ---- epilogue: two 128-co transpose passes through smem (aliased) ----
    #pragma unroll
    for (int h = 0; h < 2; h++) {
        __syncthreads();           // buffers free / prior pass stores done
        if ((nw >> 1) == h) {
            #pragma unroll
            for (int mt = 0; mt < 4; mt++) {
                int px = mw * 64 + mt * 16 + (lane >> 2);
                #pragma unroll
                for (int nt = 0; nt < 8; nt++) {
                    int co = (nw & 1) * 64 + nt * 8 + 2 * (lane & 3);
                    epi[co * 132 + px]           = acc[mt][nt][0];
                    epi[(co + 1) * 132 + px]     = acc[mt][nt][1];
                    epi[co * 132 + px + 8]       = acc[mt][nt][2];
                    epi[(co + 1) * 132 + px + 8] = acc[mt][nt][3];
                }
            }
        }
        __syncthreads();
        #pragma unroll 4
        for (int r = wid; r < 512; r += 8) {
            int co = r >> 2;               // 0..127 within pass
            int pl = (r & 3) * 32 + lane;  // local px 0..127
            int p  = p0 + pl;
            if (p < HW) {
                int cog = h * 128 + co;
                float v = epi[co * 132 + pl] * alphaS[cog];
                out[((size_t)n * COUT + cog) * HW + p] = v;
            }
        }
    }
}

// ---------------------------------------------------------------------------
extern "C" void kernel_launch(void* const* d_in, const int* in_sizes, int n_in,
                              void* d_out, int out_size) {
    const float* x     = (const float*)d_in[0];
    const float* M     = (const float*)d_in[1];
    const float* alpha = (const float*)d_in[2];
    float* out = (float*)d_out;

    {
        int total = NB * 692 * 32;
        zero_border_kernel<<<(total + 255) / 256, 256>>>();
    }
    {
        dim3 grid(2, 8, NB * H);
        bin_act_kernel<<<grid, 256>>>(x);
    }
    bin_w_kernel<<<(9 * COUT * CIN) / 256, 256>>>(M);

    cudaFuncSetAttribute(conv_mma_kernel,
                         cudaFuncAttributeMaxDynamicSharedMemorySize, SMEM_TOTAL);
    dim3 grid(25, NB, 1);
    conv_mma_kernel<<<grid, 256, SMEM_TOTAL>>>(alpha, out);
}

// round 16
// speedup vs baseline: 1.1641x; 1.1641x over previous
#include <cuda_runtime.h>
#include <cuda_bf16.h>
#include <cstdint>

// Problem constants
#define NB   32
#define CIN  256
#define COUT 256
#define H    56
#define W    56
#define HW   3136
#define HB   58   // padded rows (0..57)
#define WB   66   // padded cols (0..65)

// bf16 encodings of sign values
#define BF_P1 0x3F80u
#define BF_M1 0xBF80u

// conv staging: stage covers 64 ci: A = 128px x 128B, B = 128co x 128B
#define STG_A   16384
#define STG_SZ  32768
#define NSTAGE  3
#define SMEM_EPI_OFF 1024
#define SMEM_BUF_OFF 1024
#define SMEM_TOTAL   (1024 + NSTAGE * STG_SZ)   // 99328

// Scratch (bf16 sign values)
__device__ __align__(1024) uint16_t g_act[(size_t)NB * HB * WB * CIN];
__device__ __align__(1024) uint16_t g_wb[9 * COUT * CIN];

__device__ __forceinline__ uint16_t bsign(float v) {
    return (v > 0.f) ? (uint16_t)BF_P1 : ((v < 0.f) ? (uint16_t)BF_M1 : (uint16_t)0);
}

__device__ __forceinline__ uint32_t su32(const void* p) {
    return (uint32_t)__cvta_generic_to_shared(p);
}

#define CP16(dst, src) \
    asm volatile("cp.async.cg.shared.global [%0], [%1], 16;\n" :: "r"(dst), "l"(src))
#define CP_COMMIT() asm volatile("cp.async.commit_group;\n" ::: "memory")
#define CP_WAIT1()  asm volatile("cp.async.wait_group 1;\n" ::: "memory")

__device__ __forceinline__ void ldsm_x4(uint32_t* r, uint32_t addr) {
    asm volatile("ldmatrix.sync.aligned.m8n8.x4.shared.b16 {%0,%1,%2,%3}, [%4];"
                 : "=r"(r[0]), "=r"(r[1]), "=r"(r[2]), "=r"(r[3]) : "r"(addr));
}
__device__ __forceinline__ void mma_bf16(float* d, const uint32_t* a, const uint32_t* b) {
    asm volatile(
        "mma.sync.aligned.m16n8k16.row.col.f32.bf16.bf16.f32 "
        "{%0,%1,%2,%3}, {%4,%5,%6,%7}, {%8,%9}, {%0,%1,%2,%3};\n"
        : "+f"(d[0]), "+f"(d[1]), "+f"(d[2]), "+f"(d[3])
        : "r"(a[0]), "r"(a[1]), "r"(a[2]), "r"(a[3]), "r"(b[0]), "r"(b[1]));
}

// ---------------------------------------------------------------------------
// Zero padded borders of g_act (R7-proven).
// ---------------------------------------------------------------------------
__global__ void zero_border_kernel() {
    int idx = blockIdx.x * 256 + threadIdx.x;
    const int total = NB * 692 * 32;
    if (idx >= total) return;
    int word = idx & 31;
    int bp   = (idx >> 5) % 692;
    int n    = idx / (692 * 32);
    int yy, xx;
    if (bp < 66)       { yy = 0;  xx = bp; }
    else if (bp < 132) { yy = 57; xx = bp - 66; }
    else {
        int r = bp - 132;
        yy = 1 + r / 10;
        int c = r % 10;
        xx = (c == 0) ? 0 : (56 + c);
    }
    float4* p = reinterpret_cast<float4*>(g_act);
    p[((size_t)(n * HB + yy) * WB + xx) * 32 + word] = make_float4(0.f, 0.f, 0.f, 0.f);
}

// ---------------------------------------------------------------------------
// Binarize + transpose x (R7-proven).
// ---------------------------------------------------------------------------
__global__ void bin_act_kernel(const float* __restrict__ x) {
    __shared__ uint16_t t[32][33];
    int nz = blockIdx.z;
    int n = nz / H, y = nz % H;
    int x0 = blockIdx.x * 32;
    int c0 = blockIdx.y * 32;
    int tid = threadIdx.x;
    int tx = tid & 31, ty = tid >> 5;

    #pragma unroll
    for (int i = 0; i < 4; i++) {
        int ci = c0 + ty + i * 8;
        int xx = x0 + tx;
        float v = 0.f;
        if (xx < W)
            v = x[(((size_t)n * CIN + ci) * H + y) * W + xx];
        t[ty + i * 8][tx] = bsign(v);
    }
    __syncthreads();
    int pxi = tid >> 4;
    int cp  = tid & 15;
    #pragma unroll
    for (int j = 0; j < 2; j++) {
        int xl = pxi + j * 16;
        int xx = x0 + xl;
        if (xx < W) {
            uint32_t v = (uint32_t)t[cp * 2][xl] | ((uint32_t)t[cp * 2 + 1][xl] << 16);
            uint32_t* dst = reinterpret_cast<uint32_t*>(
                g_act + (((size_t)n * HB + (y + 1)) * WB + (xx + 1)) * CIN + c0);
            dst[cp] = v;
        }
    }
}

// ---------------------------------------------------------------------------
// Binarize weights: OIHW fp32 -> [tap][co][ci] bf16.
// ---------------------------------------------------------------------------
__global__ void bin_w_kernel(const float* __restrict__ M) {
    int o = blockIdx.x * 256 + threadIdx.x;
    int tap = o >> 16;
    int co  = (o >> 8) & 255;
    int ci  = o & 255;
    g_wb[o] = bsign(M[(size_t)(co * CIN + ci) * 9 + tap]);
}

// ---------------------------------------------------------------------------
// bf16 implicit-GEMM conv: CTA 128px x 128co with FOUR warps (128 threads),
// warp tile 64x64 -> 0.125 ldsm-x4 per MMA, stage 32KB -> 2 CTAs/SM.
// K = 9*256 in 36 stages of 64 ci; 3-buffer cp.async pipeline.
// ---------------------------------------------------------------------------
__global__ void __launch_bounds__(128, 2)
conv_mma_kernel(const float* __restrict__ alpha, float* __restrict__ out) {
    extern __shared__ char smem[];
    uint32_t sb = su32(smem);
    float* alphaS = (float*)smem;                 // 512B
    float* epi    = (float*)(smem + SMEM_EPI_OFF);

    int tid  = threadIdx.x;
    int wid  = tid >> 5, lane = tid & 31;
    int p0   = blockIdx.x * 128;
    int n    = blockIdx.y;
    int co0  = blockIdx.z * 128;

    alphaS[tid] = alpha[co0 + tid];               // 128 threads -> 128 alphas

    // ---- producer constants (128 threads) ----
    int pc = tid & 7;            // 16B chunk within 128B row (8 ci each)
    int pr = tid >> 3;           // base row 0..15 (rows pr+16i, i=0..7)
    uint32_t pdst = (uint32_t)(pr * 128) + (uint32_t)(((pc ^ (pr & 7)) << 4));
    uint32_t aoff[8];            // u32 element offsets (g_act < 2^25 elems)
    #pragma unroll
    for (int i = 0; i < 8; i++) {
        int p = p0 + pr + 16 * i;
        if (p > HW - 1) p = HW - 1;   // clamp tail tile
        int yy = p / W, xx = p - yy * W;
        aoff[i] = (uint32_t)(((n * HB + yy) * WB + xx) * CIN + pc * 8);
    }
    const uint16_t* gbBase = g_wb + (size_t)(co0 + pr) * CIN + pc * 8;

    auto produce = [&](int s) {
        if (s < 36) {
            int tap = s >> 2, q = s & 3;        // 64-ci quarter
            int kh = tap / 3, kw = tap - kh * 3;
            uint32_t tapoff = (uint32_t)((kh * WB + kw) * CIN + q * 64);
            const uint16_t* gb = gbBase + ((size_t)tap * (COUT * CIN) + q * 64);
            uint32_t base = sb + SMEM_BUF_OFF + (uint32_t)((s % 3) * STG_SZ);
            uint32_t ad = base + pdst;
            uint32_t bd = base + STG_A + pdst;
            #pragma unroll
            for (int i = 0; i < 8; i++)      // A rows pr + 16i (128 px)
                CP16(ad + i * 2048, g_act + aoff[i] + tapoff);
            #pragma unroll
            for (int i = 0; i < 8; i++)      // B rows pr + 16i (128 co)
                CP16(bd + i * 2048, gb + (size_t)i * (16 * CIN));
        }
        CP_COMMIT();
    };

    produce(0);
    produce(1);

    // ---- consumer constants: 4 warps, warp tile 64px x 64co ----
    int mw = wid & 1;            // px half (64 px)
    int nw = wid >> 1;           // co half (64 co)
    int rlA = (lane & 7) + ((lane >> 3) & 1) * 8;
    int hiA = lane >> 4;
    int swA = rlA & 7;
    int rlB = (lane & 7) + ((lane >> 4) & 1) * 8;
    int hiB = (lane >> 3) & 1;
    int swB = rlB & 7;

    float acc[4][8][4];
    #pragma unroll
    for (int mt = 0; mt < 4; mt++)
        #pragma unroll
        for (int nt = 0; nt < 8; nt++)
            #pragma unroll
            for (int c = 0; c < 4; c++) acc[mt][nt][c] = 0.f;

    for (int s = 0; s < 36; s++) {
        CP_WAIT1();
        __syncthreads();           // stage s resident; all warps done with s-1
        produce(s + 2);            // refill buf (s+2)%3 == (s-1)%3

        uint32_t aB = sb + SMEM_BUF_OFF + (uint32_t)((s % 3) * STG_SZ);
        uint32_t bB = aB + STG_A;
        #pragma unroll
        for (int kc = 0; kc < 4; kc++) {
            uint32_t a[4][4], b2[4][4];
            #pragma unroll
            for (int mt = 0; mt < 4; mt++) {
                uint32_t addr = aB + (uint32_t)((mw * 64 + mt * 16 + rlA) * 128)
                              + (uint32_t)((((kc * 2 + hiA) ^ swA) << 4));
                ldsm_x4(a[mt], addr);
            }
            #pragma unroll
            for (int np = 0; np < 4; np++) {   // 16 co each -> 64 co
                int row = nw * 64 + np * 16 + rlB;
                uint32_t addr = bB + (uint32_t)(row * 128)
                              + (uint32_t)((((kc * 2 + hiB) ^ swB) << 4));
                ldsm_x4(b2[np], addr);
            }
            #pragma unroll
            for (int mt = 0; mt < 4; mt++)
                #pragma unroll
                for (int nt = 0; nt < 8; nt++)
                    mma_bf16(acc[mt][nt], a[mt], &b2[nt >> 1][(nt & 1) * 2]);
        }
    }

    // ---- epilogue: transpose through smem, scale by alpha, coalesced stores
    __syncthreads();
    #pragma unroll
    for (int mt = 0; mt < 4; mt++) {
        int px = mw * 64 + mt * 16 + (lane >> 2);
        #pragma unroll
        for (int nt = 0; nt < 8; nt++) {
            int co = nw * 64 + nt * 8 + 2 * (lane & 3);
            epi[co * 132 + px]           = acc[mt][nt][0];
            epi[(co + 1) * 132 + px]     = acc[mt][nt][1];
            epi[co * 132 + px + 8]       = acc[mt][nt][2];
            epi[(co + 1) * 132 + px + 8] = acc[mt][nt][3];
        }
    }
    __syncthreads();

    #pragma unroll 8
    for (int r = wid; r < 512; r += 4) {
        int co = r >> 2;
        int pl = (r & 3) * 32 + lane;       // local px 0..127
        int p  = p0 + pl;
        if (p < HW) {
            float v = epi[co * 132 + pl] * alphaS[co];
            out[((size_t)n * COUT + co0 + co) * HW + p] = v;
        }
    }
}

// ---------------------------------------------------------------------------
extern "C" void kernel_launch(void* const* d_in, const int* in_sizes, int n_in,
                              void* d_out, int out_size) {
    const float* x     = (const float*)d_in[0];
    const float* M     = (const float*)d_in[1];
    const float* alpha = (const float*)d_in[2];
    float* out = (float*)d_out;

    {
        int total = NB * 692 * 32;
        zero_border_kernel<<<(total + 255) / 256, 256>>>();
    }
    {
        dim3 grid(2, 8, NB * H);
        bin_act_kernel<<<grid, 256>>>(x);
    }
    bin_w_kernel<<<(9 * COUT * CIN) / 256, 256>>>(M);

    cudaFuncSetAttribute(conv_mma_kernel,
                         cudaFuncAttributeMaxDynamicSharedMemorySize, SMEM_TOTAL);
    dim3 grid(25, NB, 2);
    conv_mma_kernel<<<grid, 128, SMEM_TOTAL>>>(alpha, out);
}

// round 17
// speedup vs baseline: 1.1953x; 1.0268x over previous
#include <cuda_runtime.h>
#include <cuda_bf16.h>
#include <cstdint>

// Problem constants
#define NB   32
#define CIN  256
#define COUT 256
#define H    56
#define W    56
#define HW   3136
#define HB   58   // padded rows (0..57)
#define WB   66   // padded cols (0..65)

// bf16 encodings of sign values
#define BF_P1 0x3F80u
#define BF_M1 0xBF80u

// conv staging: stage covers 64 ci: A = 128px x 128B, B = 128co x 128B
#define STG_A   16384
#define STG_SZ  32768
#define NSTAGE  3
#define SMEM_EPI_OFF 1024
#define SMEM_BUF_OFF 1024
#define SMEM_TOTAL   (1024 + NSTAGE * STG_SZ)   // 99328

// fused zero+binw block ranges
#define ZB_BLOCKS 2768                    // NB*692*32 / 256
#define WBK_BLOCKS 2304                   // 9*256*256 / 256

// Scratch (bf16 sign values)
__device__ __align__(1024) uint16_t g_act[(size_t)NB * HB * WB * CIN];
__device__ __align__(1024) uint16_t g_wb[9 * COUT * CIN];

__device__ __forceinline__ uint16_t bsign(float v) {
    return (v > 0.f) ? (uint16_t)BF_P1 : ((v < 0.f) ? (uint16_t)BF_M1 : (uint16_t)0);
}

__device__ __forceinline__ uint32_t su32(const void* p) {
    return (uint32_t)__cvta_generic_to_shared(p);
}

#define CP16(dst, src) \
    asm volatile("cp.async.cg.shared.global [%0], [%1], 16;\n" :: "r"(dst), "l"(src))
#define CP_COMMIT() asm volatile("cp.async.commit_group;\n" ::: "memory")
#define CP_WAIT1()  asm volatile("cp.async.wait_group 1;\n" ::: "memory")

__device__ __forceinline__ void ldsm_x4(uint32_t* r, uint32_t addr) {
    asm volatile("ldmatrix.sync.aligned.m8n8.x4.shared.b16 {%0,%1,%2,%3}, [%4];"
                 : "=r"(r[0]), "=r"(r[1]), "=r"(r[2]), "=r"(r[3]) : "r"(addr));
}
__device__ __forceinline__ void mma_bf16(float* d, const uint32_t* a, const uint32_t* b) {
    asm volatile(
        "mma.sync.aligned.m16n8k16.row.col.f32.bf16.bf16.f32 "
        "{%0,%1,%2,%3}, {%4,%5,%6,%7}, {%8,%9}, {%0,%1,%2,%3};\n"
        : "+f"(d[0]), "+f"(d[1]), "+f"(d[2]), "+f"(d[3])
        : "r"(a[0]), "r"(a[1]), "r"(a[2]), "r"(a[3]), "r"(b[0]), "r"(b[1]));
}

// ---------------------------------------------------------------------------
// Fused zero-border + binarize-weights (both tiny, no smem/barriers,
// disjoint memory regions).
// ---------------------------------------------------------------------------
__global__ void prep_small_kernel(const float* __restrict__ M) {
    int b = blockIdx.x;
    int tid = threadIdx.x;
    if (b < ZB_BLOCKS) {
        int idx = b * 256 + tid;
        int word = idx & 31;
        int bp   = (idx >> 5) % 692;
        int n    = idx / (692 * 32);
        int yy, xx;
        if (bp < 66)       { yy = 0;  xx = bp; }
        else if (bp < 132) { yy = 57; xx = bp - 66; }
        else {
            int r = bp - 132;
            yy = 1 + r / 10;
            int c = r % 10;
            xx = (c == 0) ? 0 : (56 + c);
        }
        float4* p = reinterpret_cast<float4*>(g_act);
        p[((size_t)(n * HB + yy) * WB + xx) * 32 + word] =
            make_float4(0.f, 0.f, 0.f, 0.f);
    } else {
        int o = (b - ZB_BLOCKS) * 256 + tid;
        int tap = o >> 16;
        int co  = (o >> 8) & 255;
        int ci  = o & 255;
        g_wb[o] = bsign(M[(size_t)(co * CIN + ci) * 9 + tap]);
    }
}

// ---------------------------------------------------------------------------
// Binarize + transpose x: NCHW fp32 -> padded NHWC bf16 (interior only).
// 2 y-rows per block (8 independent LDGs per thread in the read phase).
// Grid (2, 8, NB*H/2), block 256 flat.
// ---------------------------------------------------------------------------
__global__ void bin_act_kernel(const float* __restrict__ x) {
    __shared__ uint16_t t[2][32][33];
    int nz = blockIdx.z;
    int n  = nz / (H / 2);
    int y  = (nz % (H / 2)) * 2;
    int x0 = blockIdx.x * 32;
    int c0 = blockIdx.y * 32;
    int tid = threadIdx.x;
    int tx = tid & 31, ty = tid >> 5;

    #pragma unroll
    for (int i = 0; i < 4; i++) {
        int ci = c0 + ty + i * 8;
        int xx = x0 + tx;
        const float* base = x + (((size_t)n * CIN + ci) * H + y) * W + xx;
        float v0 = 0.f, v1 = 0.f;
        if (xx < W) {
            v0 = base[0];
            v1 = base[W];
        }
        t[0][ty + i * 8][tx] = bsign(v0);
        t[1][ty + i * 8][tx] = bsign(v1);
    }
    __syncthreads();
    int pxi = tid >> 4;
    int cp  = tid & 15;
    #pragma unroll
    for (int yy = 0; yy < 2; yy++) {
        #pragma unroll
        for (int j = 0; j < 2; j++) {
            int xl = pxi + j * 16;
            int xx = x0 + xl;
            if (xx < W) {
                uint32_t v = (uint32_t)t[yy][cp * 2][xl] |
                             ((uint32_t)t[yy][cp * 2 + 1][xl] << 16);
                uint32_t* dst = reinterpret_cast<uint32_t*>(
                    g_act + (((size_t)n * HB + (y + yy + 1)) * WB + (xx + 1)) * CIN + c0);
                dst[cp] = v;
            }
        }
    }
}

// ---------------------------------------------------------------------------
// bf16 implicit-GEMM conv (R16, 281 us): CTA 128px x 128co, FOUR warps,
// warp tile 64x64 -> 0.125 ldsm-x4 per MMA, stage 32KB -> 2 CTAs/SM.
// K = 9*256 in 36 stages of 64 ci; 3-buffer cp.async pipeline.
// ---------------------------------------------------------------------------
__global__ void __launch_bounds__(128, 2)
conv_mma_kernel(const float* __restrict__ alpha, float* __restrict__ out) {
    extern __shared__ char smem[];
    uint32_t sb = su32(smem);
    float* alphaS = (float*)smem;                 // 512B
    float* epi    = (float*)(smem + SMEM_EPI_OFF);

    int tid  = threadIdx.x;
    int wid  = tid >> 5, lane = tid & 31;
    int p0   = blockIdx.x * 128;
    int n    = blockIdx.y;
    int co0  = blockIdx.z * 128;

    alphaS[tid] = alpha[co0 + tid];               // 128 threads -> 128 alphas

    // ---- producer constants (128 threads) ----
    int pc = tid & 7;            // 16B chunk within 128B row (8 ci each)
    int pr = tid >> 3;           // base row 0..15 (rows pr+16i, i=0..7)
    uint32_t pdst = (uint32_t)(pr * 128) + (uint32_t)(((pc ^ (pr & 7)) << 4));
    uint32_t aoff[8];            // u32 element offsets
    #pragma unroll
    for (int i = 0; i < 8; i++) {
        int p = p0 + pr + 16 * i;
        if (p > HW - 1) p = HW - 1;   // clamp tail tile
        int yy = p / W, xx = p - yy * W;
        aoff[i] = (uint32_t)(((n * HB + yy) * WB + xx) * CIN + pc * 8);
    }
    const uint16_t* gbBase = g_wb + (size_t)(co0 + pr) * CIN + pc * 8;

    auto produce = [&](int s) {
        if (s < 36) {
            int tap = s >> 2, q = s & 3;        // 64-ci quarter
            int kh = tap / 3, kw = tap - kh * 3;
            uint32_t tapoff = (uint32_t)((kh * WB + kw) * CIN + q * 64);
            const uint16_t* gb = gbBase + ((size_t)tap * (COUT * CIN) + q * 64);
            uint32_t base = sb + SMEM_BUF_OFF + (uint32_t)((s % 3) * STG_SZ);
            uint32_t ad = base + pdst;
            uint32_t bd = base + STG_A + pdst;
            #pragma unroll
            for (int i = 0; i < 8; i++)      // A rows pr + 16i (128 px)
                CP16(ad + i * 2048, g_act + aoff[i] + tapoff);
            #pragma unroll
            for (int i = 0; i < 8; i++)      // B rows pr + 16i (128 co)
                CP16(bd + i * 2048, gb + (size_t)i * (16 * CIN));
        }
        CP_COMMIT();
    };

    produce(0);
    produce(1);

    // ---- consumer constants: 4 warps, warp tile 64px x 64co ----
    int mw = wid & 1;            // px half (64 px)
    int nw = wid >> 1;           // co half (64 co)
    int rlA = (lane & 7) + ((lane >> 3) & 1) * 8;
    int hiA = lane >> 4;
    int swA = rlA & 7;
    int rlB = (lane & 7) + ((lane >> 4) & 1) * 8;
    int hiB = (lane >> 3) & 1;
    int swB = rlB & 7;

    float acc[4][8][4];
    #pragma unroll
    for (int mt = 0; mt < 4; mt++)
        #pragma unroll
        for (int nt = 0; nt < 8; nt++)
            #pragma unroll
            for (int c = 0; c < 4; c++) acc[mt][nt][c] = 0.f;

    for (int s = 0; s < 36; s++) {
        CP_WAIT1();
        __syncthreads();           // stage s resident; all warps done with s-1
        produce(s + 2);            // refill buf (s+2)%3 == (s-1)%3

        uint32_t aB = sb + SMEM_BUF_OFF + (uint32_t)((s % 3) * STG_SZ);
        uint32_t bB = aB + STG_A;
        #pragma unroll
        for (int kc = 0; kc < 4; kc++) {
            uint32_t a[4][4], b2[4][4];
            #pragma unroll
            for (int mt = 0; mt < 4; mt++) {
                uint32_t addr = aB + (uint32_t)((mw * 64 + mt * 16 + rlA) * 128)
                              + (uint32_t)((((kc * 2 + hiA) ^ swA) << 4));
                ldsm_x4(a[mt], addr);
            }
            #pragma unroll
            for (int np = 0; np < 4; np++) {   // 16 co each -> 64 co
                int row = nw * 64 + np * 16 + rlB;
                uint32_t addr = bB + (uint32_t)(row * 128)
                              + (uint32_t)((((kc * 2 + hiB) ^ swB) << 4));
                ldsm_x4(b2[np], addr);
            }
            #pragma unroll
            for (int mt = 0; mt < 4; mt++)
                #pragma unroll
                for (int nt = 0; nt < 8; nt++)
                    mma_bf16(acc[mt][nt], a[mt], &b2[nt >> 1][(nt & 1) * 2]);
        }
    }

    // ---- epilogue: transpose through smem, scale by alpha, coalesced stores
    __syncthreads();
    #pragma unroll
    for (int mt = 0; mt < 4; mt++) {
        int px = mw * 64 + mt * 16 + (lane >> 2);
        #pragma unroll
        for (int nt = 0; nt < 8; nt++) {
            int co = nw * 64 + nt * 8 + 2 * (lane & 3);
            epi[co * 132 + px]           = acc[mt][nt][0];
            epi[(co + 1) * 132 + px]     = acc[mt][nt][1];
            epi[co * 132 + px + 8]       = acc[mt][nt][2];
            epi[(co + 1) * 132 + px + 8] = acc[mt][nt][3];
        }
    }
    __syncthreads();

    #pragma unroll 8
    for (int r = wid; r < 512; r += 4) {
        int co = r >> 2;
        int pl = (r & 3) * 32 + lane;       // local px 0..127
        int p  = p0 + pl;
        if (p < HW) {
            float v = epi[co * 132 + pl] * alphaS[co];
            out[((size_t)n * COUT + co0 + co) * HW + p] = v;
        }
    }
}

// ---------------------------------------------------------------------------
extern "C" void kernel_launch(void* const* d_in, const int* in_sizes, int n_in,
                              void* d_out, int out_size) {
    const float* x     = (const float*)d_in[0];
    const float* M     = (const float*)d_in[1];
    const float* alpha = (const float*)d_in[2];
    float* out = (float*)d_out;

    prep_small_kernel<<<ZB_BLOCKS + WBK_BLOCKS, 256>>>(M);
    {
        dim3 grid(2, 8, NB * H / 2);
        bin_act_kernel<<<grid, 256>>>(x);
    }

    cudaFuncSetAttribute(conv_mma_kernel,
                         cudaFuncAttributeMaxDynamicSharedMemorySize, SMEM_TOTAL);
    dim3 grid(25, NB, 2);
    conv_mma_kernel<<<grid, 128, SMEM_TOTAL>>>(alpha, out);
}